// round 1
// baseline (speedup 1.0000x reference)
#include <cuda_runtime.h>

#define PNUM   1024
#define BNUM   8
#define NB     11
#define NBINS  (NB*NB*NB)   // 1331
#define IPB    16           // i-rows per block
#define THREADS 256

// Scratch: integer histogram per batch (no device allocation allowed -> __device__ global)
__device__ int g_hist[BNUM * NBINS];

__global__ void fpfh_zero_kernel() {
    int t = blockIdx.x * blockDim.x + threadIdx.x;
    if (t < BNUM * NBINS) g_hist[t] = 0;
}

__global__ __launch_bounds__(THREADS) void fpfh_accum_kernel(const float* __restrict__ x) {
    __shared__ float s_px[PNUM], s_py[PNUM], s_pz[PNUM];
    __shared__ float s_ox[PNUM], s_oy[PNUM], s_oz[PNUM];
    __shared__ int   s_hist[NBINS];

    const int b     = blockIdx.y;
    const int chunk = blockIdx.x;

    // Load the entire batch (1024 points x 6 floats = 24KB) into SoA shared.
    const float* __restrict__ base = x + (size_t)b * PNUM * 6;
    for (int t = threadIdx.x; t < PNUM * 6; t += THREADS) {
        float v = base[t];
        int p = t / 6, c = t % 6;
        switch (c) {
            case 0: s_px[p] = v; break;
            case 1: s_py[p] = v; break;
            case 2: s_pz[p] = v; break;
            case 3: s_ox[p] = v; break;
            case 4: s_oy[p] = v; break;
            default: s_oz[p] = v; break;
        }
    }
    for (int t = threadIdx.x; t < NBINS; t += THREADS) s_hist[t] = 0;
    __syncthreads();

    const float eps    = 1e-6f;
    const float pi_f32 = 3.14159265358979323846f; // rounds to 0x40490FDB, same as jnp.pi->f32

    #pragma unroll 1
    for (int ii = 0; ii < IPB; ii++) {
        const int i = chunk * IPB + ii;
        const float pix = s_px[i], piy = s_py[i], piz = s_pz[i];
        const float nix = s_ox[i], niy = s_oy[i], niz = s_oz[i];

        for (int j = threadIdx.x; j < PNUM; j += THREADS) {
            if (j == i) continue;  // diagonal weight = 0

            // delta[b,i,j] = pos[b,j] - pos[b,i]
            const float dx = s_px[j] - pix;
            const float dy = s_py[j] - piy;
            const float dz = s_pz[j] - piz;
            const float njx = s_ox[j], njy = s_oy[j], njz = s_oz[j];

            const float dist = sqrtf(dx*dx + dy*dy + dz*dz);

            // v = cross(delta, ni), normalized with +eps
            float vx = dy*niz - dz*niy;
            float vy = dz*nix - dx*niz;
            float vz = dx*niy - dy*nix;
            const float vn = sqrtf(vx*vx + vy*vy + vz*vz) + eps;
            vx /= vn; vy /= vn; vz /= vn;

            // w = cross(ni, v), normalized with +eps
            float wx = niy*vz - niz*vy;
            float wy = niz*vx - nix*vz;
            float wz = nix*vy - niy*vx;
            const float wn = sqrtf(wx*wx + wy*wy + wz*wz) + eps;
            wx /= wn; wy /= wn; wz /= wn;

            const float alpha = vx*njx + vy*njy + vz*njz;
            const float phi   = (nix*dx + niy*dy + niz*dz) / (dist + eps);
            const float theta = atan2f(wx*njx + wy*njy + wz*njz,
                                       nix*njx + niy*njy + niz*njz) / pi_f32;

            // to_idx: trunc-toward-zero cast (matches astype(int32)), clamp top only
            int ai = (int)((alpha + 1.0f) * 0.5f * 11.0f); ai = min(ai, NB - 1);
            int pidx = (int)((phi + 1.0f) * 0.5f * 11.0f); pidx = min(pidx, NB - 1);
            int ti = (int)((theta + 1.0f) * 0.5f * 11.0f); ti = min(ti, NB - 1);

            int idx = (ai * NB + pidx) * NB + ti;
            // JAX advanced-index semantics: one negative wrap, then OOB scatter drops
            if (idx < 0) idx += NBINS;
            if ((unsigned)idx < (unsigned)NBINS) atomicAdd(&s_hist[idx], 1);
        }
    }
    __syncthreads();

    // Flush block-private histogram to global
    for (int t = threadIdx.x; t < NBINS; t += THREADS) {
        int c = s_hist[t];
        if (c) atomicAdd(&g_hist[b * NBINS + t], c);
    }
}

__global__ void fpfh_finalize_kernel(float* __restrict__ out) {
    int t = blockIdx.x * blockDim.x + threadIdx.x;
    if (t < BNUM * NBINS) {
        // freq = count / (P*(P-1)); true f32 division to match reference
        out[t] = (float)g_hist[t] / 1047552.0f;  // 1024*1023
    }
}

extern "C" void kernel_launch(void* const* d_in, const int* in_sizes, int n_in,
                              void* d_out, int out_size) {
    const float* x = (const float*)d_in[0];
    float* out = (float*)d_out;

    int total = BNUM * NBINS;
    fpfh_zero_kernel<<<(total + 255) / 256, 256>>>();

    dim3 grid(PNUM / IPB, BNUM);   // 64 x 8 = 512 blocks
    fpfh_accum_kernel<<<grid, THREADS>>>(x);

    fpfh_finalize_kernel<<<(total + 255) / 256, 256>>>(out);
}

// round 2
// speedup vs baseline: 1.7267x; 1.7267x over previous
#include <cuda_runtime.h>

#define PNUM    1024
#define BNUM    8
#define NB      11
#define NBINS   (NB*NB*NB)   // 1331
#define IPB     8            // i-rows per block
#define THREADS 256
#define JSTEPS  (PNUM / THREADS)  // 4

// Per-batch integer histogram scratch (zero-initialized at module load;
// finalize kernel resets it after each read so every graph replay is clean).
__device__ int g_hist[BNUM * NBINS];

// Fast atan2: degree-11 minimax polynomial, max err ~1e-6 rad.
__device__ __forceinline__ float fast_atan2f(float y, float x) {
    const float a1  =  0.99997726f;
    const float a3  = -0.33262347f;
    const float a5  =  0.19354346f;
    const float a7  = -0.11643287f;
    const float a9  =  0.05265332f;
    const float a11 = -0.01172120f;

    float ax = fabsf(x), ay = fabsf(y);
    float mx = fmaxf(ax, ay), mn = fminf(ax, ay);
    float t  = __fdividef(mn, mx);          // in [0,1]
    float t2 = t * t;
    float p  = fmaf(t2, a11, a9);
    p = fmaf(t2, p, a7);
    p = fmaf(t2, p, a5);
    p = fmaf(t2, p, a3);
    p = fmaf(t2, p, a1);
    float r = p * t;                         // atan(mn/mx)
    if (ay > ax)   r = 1.57079637f - r;      // first-octant fixup
    if (x < 0.0f)  r = 3.14159274f - r;
    return copysignf(r, y);
}

__global__ __launch_bounds__(THREADS) void fpfh_accum_kernel(const float* __restrict__ x) {
    __shared__ float s_px[PNUM], s_py[PNUM], s_pz[PNUM];
    __shared__ float s_ox[PNUM], s_oy[PNUM], s_oz[PNUM];
    __shared__ int   s_hist[NBINS];

    const int b     = blockIdx.y;
    const int chunk = blockIdx.x;

    // Load the entire batch (1024 points x 6 floats = 24KB) into SoA shared.
    const float* __restrict__ base = x + (size_t)b * PNUM * 6;
    for (int t = threadIdx.x; t < PNUM * 6; t += THREADS) {
        float v = base[t];
        int p = t / 6, c = t % 6;
        switch (c) {
            case 0: s_px[p] = v; break;
            case 1: s_py[p] = v; break;
            case 2: s_pz[p] = v; break;
            case 3: s_ox[p] = v; break;
            case 4: s_oy[p] = v; break;
            default: s_oz[p] = v; break;
        }
    }
    for (int t = threadIdx.x; t < NBINS; t += THREADS) s_hist[t] = 0;
    __syncthreads();

    const float eps   = 1e-6f;
    const float invpi = 0.31830987f;  // f32(1/pi); <=1ulp vs /pi

    #pragma unroll 1
    for (int ii = 0; ii < IPB; ii++) {
        const int i = chunk * IPB + ii;
        const float pix = s_px[i], piy = s_py[i], piz = s_pz[i];
        const float nix = s_ox[i], niy = s_oy[i], niz = s_oz[i];

        #pragma unroll
        for (int jj = 0; jj < JSTEPS; jj++) {
            const int j = threadIdx.x + jj * THREADS;

            // delta = pos[j] - pos[i]
            const float dx = s_px[j] - pix;
            const float dy = s_py[j] - piy;
            const float dz = s_pz[j] - piz;
            const float njx = s_ox[j], njy = s_oy[j], njz = s_oz[j];

            const float d2   = fmaf(dx, dx, fmaf(dy, dy, dz * dz));
            const float dist = d2 * rsqrtf(d2);          // sqrt(d2), i!=j => d2>0

            // v_raw = cross(delta, ni); vn = |v_raw| + eps
            const float vx = dy * niz - dz * niy;
            const float vy = dz * nix - dx * niz;
            const float vz = dx * niy - dy * nix;
            const float v2 = fmaf(vx, vx, fmaf(vy, vy, vz * vz));
            const float vn = v2 * rsqrtf(v2) + eps;
            const float inv_vn = __fdividef(1.0f, vn);

            // w_raw = cross(ni, v_raw); normalized w = w_raw*inv_vn / (|w_raw|*inv_vn + eps)
            const float wx = niy * vz - niz * vy;
            const float wy = niz * vx - nix * vz;
            const float wz = nix * vy - niy * vx;
            const float w2 = fmaf(wx, wx, fmaf(wy, wy, wz * wz));
            const float wn = (w2 * rsqrtf(w2)) * inv_vn + eps;
            const float inv_wn = __fdividef(1.0f, wn);

            const float alpha = fmaf(vx, njx, fmaf(vy, njy, vz * njz)) * inv_vn;
            const float phi   = __fdividef(fmaf(nix, dx, fmaf(niy, dy, niz * dz)), dist + eps);
            const float wdot  = fmaf(wx, njx, fmaf(wy, njy, wz * njz)) * inv_vn * inv_wn;
            const float ndot  = fmaf(nix, njx, fmaf(niy, njy, niz * njz));
            const float theta = fast_atan2f(wdot, ndot) * invpi;

            // to_idx: trunc-toward-zero (matches astype(int32)), clamp top only
            int ai = (int)((alpha + 1.0f) * 0.5f * 11.0f); ai = min(ai, NB - 1);
            int pi = (int)((phi   + 1.0f) * 0.5f * 11.0f); pi = min(pi, NB - 1);
            int ti = (int)((theta + 1.0f) * 0.5f * 11.0f); ti = min(ti, NB - 1);

            int idx = (ai * NB + pi) * NB + ti;
            if (idx < 0) idx += NBINS;            // JAX: single negative wrap
            // drop OOB (JAX scatter FILL_OR_DROP) and the i==j diagonal
            if ((unsigned)idx < (unsigned)NBINS && j != i)
                atomicAdd(&s_hist[idx], 1);
        }
    }
    __syncthreads();

    // Flush block-private histogram to the per-batch global histogram.
    for (int t = threadIdx.x; t < NBINS; t += THREADS) {
        int c = s_hist[t];
        if (c) atomicAdd(&g_hist[b * NBINS + t], c);
    }
}

__global__ void fpfh_finalize_kernel(float* __restrict__ out) {
    int t = blockIdx.x * blockDim.x + threadIdx.x;
    if (t < BNUM * NBINS) {
        out[t] = (float)g_hist[t] / 1047552.0f;  // / (1024*1023)
        g_hist[t] = 0;                           // reset for next replay
    }
}

extern "C" void kernel_launch(void* const* d_in, const int* in_sizes, int n_in,
                              void* d_out, int out_size) {
    const float* x = (const float*)d_in[0];
    float* out = (float*)d_out;

    dim3 grid(PNUM / IPB, BNUM);   // 128 x 8 = 1024 blocks
    fpfh_accum_kernel<<<grid, THREADS>>>(x);

    int total = BNUM * NBINS;
    fpfh_finalize_kernel<<<(total + 255) / 256, 256>>>(out);
}